// round 15
// baseline (speedup 1.0000x reference)
#include <cuda_runtime.h>
#include <cuda_fp16.h>
#include <mma.h>

using namespace nvcuda;

// ---------------------------------------------------------------------------
// EdgeDecoder: out[e] = relu([zu[row]; zr[col]] @ W1 + b1) @ W2 + b2
// U = zu @ W1_top + b1 ; R = zr @ W1_bot  (fp16 HMMA, fp32 acc). U,R fp16.
// R15: maxrow scan folded into precompute_R as a per-block prologue (R-GEMM
//      has no maxrow dependency; U-GEMM launches after and reads g_maxrow).
//      Removes the standalone maxrow launch (~7us incl. launch overhead).
// ---------------------------------------------------------------------------

#define HDIM 128
#define MAX_USER   100000
#define MAX_RECIPE 50000

__device__ __half g_U[(size_t)MAX_USER * HDIM];    // 25.6 MB
__device__ __half g_R[(size_t)MAX_RECIPE * HDIM];  // 12.8 MB
__device__ int    g_is64;
__device__ int    g_maxrow;          // zero-init; atomicMax, idempotent

#define APITCH 136
#define TILEB  (128 * APITCH * 2)
#define CPITCH 132

// ---------------------------------------------------------------------------
__device__ __forceinline__ int detect_is64_block(const unsigned long long* p) {
    __shared__ int s_is64;
    if (threadIdx.x == 0) {
        int v = 1;
        #pragma unroll
        for (int i = 0; i < 32; ++i)
            if ((p[i] >> 32) != 0ull) v = 0;
        s_is64 = v;
    }
    __syncthreads();
    return s_is64;
}

// ---------------------------------------------------------------------------
// Shared GEMM tile body: C[row0:row0+128] = Z @ Wp (+bias), fp16 HMMA.
// ---------------------------------------------------------------------------
__device__ __forceinline__ void gemm_tile(const float* __restrict__ Z,
                                          const float* __restrict__ Wp,
                                          const float* __restrict__ bias,
                                          __half* __restrict__ C,
                                          int row0, int M, char* sm)
{
    __half* Ah = (__half*)sm;
    __half* Bh = (__half*)(sm + TILEB);
    const int tid = threadIdx.x;

    #pragma unroll
    for (int idx = tid; idx < 4096; idx += 512) {
        const int r  = idx >> 5;
        const int c4 = (idx & 31) * 4;
        float4 v = ((const float4*)Wp)[idx];
        __half2 p0 = __float22half2_rn(make_float2(v.x, v.y));
        __half2 p1 = __float22half2_rn(make_float2(v.z, v.w));
        uint2 hh; hh.x = *(unsigned*)&p0; hh.y = *(unsigned*)&p1;
        *(uint2*)&Bh[r * APITCH + c4] = hh;
    }
    #pragma unroll
    for (int idx = tid; idx < 4096; idx += 512) {
        const int r  = idx >> 5;
        const int c4 = (idx & 31) * 4;
        const int gr = row0 + r;
        float4 v = make_float4(0.f, 0.f, 0.f, 0.f);
        if (gr < M) v = ((const float4*)Z)[(size_t)gr * 32 + (idx & 31)];
        __half2 p0 = __float22half2_rn(make_float2(v.x, v.y));
        __half2 p1 = __float22half2_rn(make_float2(v.z, v.w));
        uint2 hh; hh.x = *(unsigned*)&p0; hh.y = *(unsigned*)&p1;
        *(uint2*)&Ah[r * APITCH + c4] = hh;
    }
    __syncthreads();

    const int warp = tid >> 5;
    const int wm   = warp >> 1;
    const int wn   = warp & 1;

    wmma::fragment<wmma::accumulator, 16, 16, 16, float> acc[4];
    #pragma unroll
    for (int j = 0; j < 4; ++j) wmma::fill_fragment(acc[j], 0.f);

    wmma::fragment<wmma::matrix_a, 16, 16, 16, __half, wmma::row_major> fA;
    wmma::fragment<wmma::matrix_b, 16, 16, 16, __half, wmma::row_major> fB;

    #pragma unroll
    for (int k = 0; k < HDIM; k += 16) {
        wmma::load_matrix_sync(fA, Ah + (wm * 16) * APITCH + k, APITCH);
        #pragma unroll
        for (int j = 0; j < 4; ++j) {
            wmma::load_matrix_sync(fB, Bh + k * APITCH + wn * 64 + j * 16, APITCH);
            wmma::mma_sync(acc[j], fA, fB, acc[j]);
        }
    }

    __syncthreads();
    float* Cf = (float*)sm;
    #pragma unroll
    for (int j = 0; j < 4; ++j)
        wmma::store_matrix_sync(Cf + (wm * 16) * CPITCH + wn * 64 + j * 16,
                                acc[j], CPITCH, wmma::mem_row_major);
    __syncthreads();

    #pragma unroll
    for (int idx = tid; idx < 4096; idx += 512) {
        const int r  = idx >> 5;
        const int c4 = (idx & 31) * 4;
        const int gr = row0 + r;
        if (gr < M) {
            float4 v = *(const float4*)&Cf[r * CPITCH + c4];
            if (bias) {
                const float4 bv = *(const float4*)&bias[c4];
                v.x += bv.x; v.y += bv.y; v.z += bv.z; v.w += bv.w;
            }
            __half2 h0 = __float22half2_rn(make_float2(v.x, v.y));
            __half2 h1 = __float22half2_rn(make_float2(v.z, v.w));
            uint2 o; o.x = *(unsigned*)&h0; o.y = *(unsigned*)&h1;
            *(uint2*)&C[(size_t)gr * HDIM + c4] = o;
        }
    }
}

// ---------------------------------------------------------------------------
// Kernel 1: R GEMM + maxrow-scan prologue (rides along; no extra launch).
// Rows are >=0 and < 2^31, so signed max over raw 32-bit words is exact for
// both index dtypes (int64 high words are zero; int32 words are all values).
// ---------------------------------------------------------------------------
__global__ __launch_bounds__(512, 2)
void precompute_R_kernel(const float* __restrict__ Zr,
                         const float* __restrict__ W1,
                         const void* __restrict__ eidx,
                         int E, int Mr)
{
    extern __shared__ __align__(16) char sm[];

    const int is64 = detect_is64_block((const unsigned long long*)eidx);
    if (blockIdx.x == 0 && threadIdx.x == 0) g_is64 = is64;

    // maxrow prologue: this block's coalesced slice of the row region.
    {
        const size_t nwords = (size_t)E * (is64 ? 2 : 1);
        const int n4 = (int)(nwords >> 2);
        const uint4* p4 = (const uint4*)eidx;
        const int chunk = (n4 + gridDim.x - 1) / gridDim.x;
        const int beg = blockIdx.x * chunk;
        const int end = min(beg + chunk, n4);
        int m = 0;
        for (int i = beg + threadIdx.x; i < end; i += 512) {
            uint4 a = p4[i];
            m = max(m, max(max((int)a.x, (int)a.y), max((int)a.z, (int)a.w)));
        }
        if (blockIdx.x == 0) {       // scalar word tail
            const int* pw = (const int*)eidx;
            for (int w = (n4 << 2) + threadIdx.x; w < (int)nwords; w += 512)
                m = max(m, pw[w]);
        }
        #pragma unroll
        for (int off = 16; off; off >>= 1)
            m = max(m, __shfl_xor_sync(0xffffffffu, m, off));
        if ((threadIdx.x & 31) == 0) atomicMax(&g_maxrow, m);
    }

    gemm_tile(Zr, W1 + HDIM * HDIM, nullptr, g_R, blockIdx.x * 128, Mr, sm);
}

// ---------------------------------------------------------------------------
// Kernel 2: U GEMM; tiles beyond g_maxrow (set by kernel 1) exit immediately.
// ---------------------------------------------------------------------------
__global__ __launch_bounds__(512, 2)
void precompute_U_kernel(const float* __restrict__ Zu,
                         const float* __restrict__ W1,
                         const float* __restrict__ b1,
                         int Mu)
{
    extern __shared__ __align__(16) char sm[];
    const int row0 = blockIdx.x * 128;
    if (row0 > g_maxrow) return;
    gemm_tile(Zu, W1, b1, g_U, row0, Mu, sm);
}

// ---------------------------------------------------------------------------
// Phase 2: four edges per warp (8 lanes each); lane l8 loads chunks l8 and
// l8+8 so each 8-lane LDG.128 group covers one full 128B line.
// ---------------------------------------------------------------------------
__device__ __forceinline__ float dot8h(uint4 u, uint4 r, float4 w0, float4 w1) {
    const __half2 z2 = __float2half2_rn(0.f);
    __half2 a0 = __hmax2(__hadd2(*(__half2*)&u.x, *(__half2*)&r.x), z2);
    __half2 a1 = __hmax2(__hadd2(*(__half2*)&u.y, *(__half2*)&r.y), z2);
    __half2 a2 = __hmax2(__hadd2(*(__half2*)&u.z, *(__half2*)&r.z), z2);
    __half2 a3 = __hmax2(__hadd2(*(__half2*)&u.w, *(__half2*)&r.w), z2);
    float2 f0 = __half22float2(a0);
    float2 f1 = __half22float2(a1);
    float2 f2 = __half22float2(a2);
    float2 f3 = __half22float2(a3);
    float s;
    s  = f0.x * w0.x;
    s  = fmaf(f0.y, w0.y, s);
    s  = fmaf(f1.x, w0.z, s);
    s  = fmaf(f1.y, w0.w, s);
    s  = fmaf(f2.x, w1.x, s);
    s  = fmaf(f2.y, w1.y, s);
    s  = fmaf(f3.x, w1.z, s);
    s  = fmaf(f3.y, w1.w, s);
    return s;
}

__global__ __launch_bounds__(256)
void edge_kernel(const void* __restrict__ eidx,
                 const float* __restrict__ W2,
                 const float* __restrict__ b2,
                 float* __restrict__ out,
                 int E)
{
    __shared__ float w2s[HDIM];
    const int tid = threadIdx.x;
    if (tid < HDIM) w2s[tid] = W2[tid];
    __syncthreads();

    const int warp = (blockIdx.x * 256 + tid) >> 5;
    const int lane = tid & 31;
    const int sub  = lane >> 3;
    const int l8   = lane & 7;
    const int e    = warp * 4 + sub;
    if (e >= E) return;

    int row, col;
    if (g_is64) {
        const long long* p = (const long long*)eidx;
        row = (int)p[e];
        col = (int)p[(size_t)E + e];
    } else {
        const int* p = (const int*)eidx;
        row = p[e];
        col = p[(size_t)E + e];
    }

    const uint4* Up = (const uint4*)&g_U[(size_t)row * HDIM];
    const uint4* Rp = (const uint4*)&g_R[(size_t)col * HDIM];
    const uint4 ua = Up[l8],  ub = Up[l8 + 8];
    const uint4 ra = Rp[l8],  rb = Rp[l8 + 8];

    const float4* w4 = (const float4*)w2s;
    const float4 w0 = w4[2 * l8],      w1 = w4[2 * l8 + 1];
    const float4 w2 = w4[16 + 2 * l8], w3 = w4[16 + 2 * l8 + 1];

    float s = dot8h(ua, ra, w0, w1) + dot8h(ub, rb, w2, w3);

    const unsigned mask = 0xFFu << (sub * 8);
    #pragma unroll
    for (int off = 4; off; off >>= 1)
        s += __shfl_xor_sync(mask, s, off);

    if (l8 == 0) out[e] = s + __ldg(b2);
}

// ---------------------------------------------------------------------------
extern "C" void kernel_launch(void* const* d_in, const int* in_sizes, int n_in,
                              void* d_out, int out_size)
{
    const float* z_user   = (const float*)d_in[0];
    const float* z_recipe = (const float*)d_in[1];
    const void*  eidx     = d_in[2];
    const float* W1       = (const float*)d_in[3];
    const float* b1       = (const float*)d_in[4];
    const float* W2       = (const float*)d_in[5];
    const float* b2       = (const float*)d_in[6];
    float* out = (float*)d_out;

    const int Mu = in_sizes[0] / HDIM;
    const int Mr = in_sizes[1] / HDIM;
    const int E  = in_sizes[2] / 2;

    const int SMEM = 2 * TILEB;
    cudaFuncSetAttribute(precompute_R_kernel,
                         cudaFuncAttributeMaxDynamicSharedMemorySize, SMEM);
    cudaFuncSetAttribute(precompute_U_kernel,
                         cudaFuncAttributeMaxDynamicSharedMemorySize, SMEM);

    const int gu = (Mu + 127) / 128;
    const int gr = (Mr + 127) / 128;

    precompute_R_kernel<<<gr, 512, SMEM>>>(z_recipe, W1, eidx, E, Mr);
    precompute_U_kernel<<<gu, 512, SMEM>>>(z_user, W1, b1, Mu);
    edge_kernel<<<(E + 31) / 32, 256>>>(eidx, W2, b2, out, E);
}

// round 16
// speedup vs baseline: 1.0049x; 1.0049x over previous
#include <cuda_runtime.h>
#include <cuda_fp16.h>
#include <mma.h>

using namespace nvcuda;

// ---------------------------------------------------------------------------
// EdgeDecoder: out[e] = relu([zu[row]; zr[col]] @ W1 + b1) @ W2 + b2
// U = zu @ W1_top + b1 ; R = zr @ W1_bot  (fp16 HMMA, fp32 acc). U,R fp16.
// R16: single combined GEMM launch (R tiles + first K=min(gu,gr) U tiles,
//      which cover all rows < Mr unconditionally) with the maxrow scan as a
//      distributed, block-reduced prologue. U remainder kernel (gated on
//      g_maxrow) normally all-skips. Restores R14's 2.64-wave packing while
//      keeping the standalone maxrow launch deleted.
// ---------------------------------------------------------------------------

#define HDIM 128
#define MAX_USER   100000
#define MAX_RECIPE 50000

__device__ __half g_U[(size_t)MAX_USER * HDIM];    // 25.6 MB
__device__ __half g_R[(size_t)MAX_RECIPE * HDIM];  // 12.8 MB
__device__ int    g_is64;
__device__ int    g_maxrow;          // zero-init; atomicMax, idempotent

#define APITCH 136
#define TILEB  (128 * APITCH * 2)
#define CPITCH 132

// ---------------------------------------------------------------------------
__device__ __forceinline__ int detect_is64_block(const unsigned long long* p) {
    __shared__ int s_is64;
    if (threadIdx.x == 0) {
        int v = 1;
        #pragma unroll
        for (int i = 0; i < 32; ++i)
            if ((p[i] >> 32) != 0ull) v = 0;
        s_is64 = v;
    }
    __syncthreads();
    return s_is64;
}

// ---------------------------------------------------------------------------
// Shared GEMM tile body: C[row0:row0+128] = Z @ Wp (+bias), fp16 HMMA.
// ---------------------------------------------------------------------------
__device__ __forceinline__ void gemm_tile(const float* __restrict__ Z,
                                          const float* __restrict__ Wp,
                                          const float* __restrict__ bias,
                                          __half* __restrict__ C,
                                          int row0, int M, char* sm)
{
    __half* Ah = (__half*)sm;
    __half* Bh = (__half*)(sm + TILEB);
    const int tid = threadIdx.x;

    #pragma unroll
    for (int idx = tid; idx < 4096; idx += 512) {
        const int r  = idx >> 5;
        const int c4 = (idx & 31) * 4;
        float4 v = ((const float4*)Wp)[idx];
        __half2 p0 = __float22half2_rn(make_float2(v.x, v.y));
        __half2 p1 = __float22half2_rn(make_float2(v.z, v.w));
        uint2 hh; hh.x = *(unsigned*)&p0; hh.y = *(unsigned*)&p1;
        *(uint2*)&Bh[r * APITCH + c4] = hh;
    }
    #pragma unroll
    for (int idx = tid; idx < 4096; idx += 512) {
        const int r  = idx >> 5;
        const int c4 = (idx & 31) * 4;
        const int gr = row0 + r;
        float4 v = make_float4(0.f, 0.f, 0.f, 0.f);
        if (gr < M) v = ((const float4*)Z)[(size_t)gr * 32 + (idx & 31)];
        __half2 p0 = __float22half2_rn(make_float2(v.x, v.y));
        __half2 p1 = __float22half2_rn(make_float2(v.z, v.w));
        uint2 hh; hh.x = *(unsigned*)&p0; hh.y = *(unsigned*)&p1;
        *(uint2*)&Ah[r * APITCH + c4] = hh;
    }
    __syncthreads();

    const int warp = tid >> 5;
    const int wm   = warp >> 1;
    const int wn   = warp & 1;

    wmma::fragment<wmma::accumulator, 16, 16, 16, float> acc[4];
    #pragma unroll
    for (int j = 0; j < 4; ++j) wmma::fill_fragment(acc[j], 0.f);

    wmma::fragment<wmma::matrix_a, 16, 16, 16, __half, wmma::row_major> fA;
    wmma::fragment<wmma::matrix_b, 16, 16, 16, __half, wmma::row_major> fB;

    #pragma unroll
    for (int k = 0; k < HDIM; k += 16) {
        wmma::load_matrix_sync(fA, Ah + (wm * 16) * APITCH + k, APITCH);
        #pragma unroll
        for (int j = 0; j < 4; ++j) {
            wmma::load_matrix_sync(fB, Bh + k * APITCH + wn * 64 + j * 16, APITCH);
            wmma::mma_sync(acc[j], fA, fB, acc[j]);
        }
    }

    __syncthreads();
    float* Cf = (float*)sm;
    #pragma unroll
    for (int j = 0; j < 4; ++j)
        wmma::store_matrix_sync(Cf + (wm * 16) * CPITCH + wn * 64 + j * 16,
                                acc[j], CPITCH, wmma::mem_row_major);
    __syncthreads();

    #pragma unroll
    for (int idx = tid; idx < 4096; idx += 512) {
        const int r  = idx >> 5;
        const int c4 = (idx & 31) * 4;
        const int gr = row0 + r;
        if (gr < M) {
            float4 v = *(const float4*)&Cf[r * CPITCH + c4];
            if (bias) {
                const float4 bv = *(const float4*)&bias[c4];
                v.x += bv.x; v.y += bv.y; v.z += bv.z; v.w += bv.w;
            }
            __half2 h0 = __float22half2_rn(make_float2(v.x, v.y));
            __half2 h1 = __float22half2_rn(make_float2(v.z, v.w));
            uint2 o; o.x = *(unsigned*)&h0; o.y = *(unsigned*)&h1;
            *(uint2*)&C[(size_t)gr * HDIM + c4] = o;
        }
    }
}

// ---------------------------------------------------------------------------
// Kernel A: blocks [0,gr) = R tiles; blocks [gr, gr+K) = U tiles [0,K)
// (unconditional: rows < Mr are always covered by K=min(gu,gr) tiles).
// Distributed maxrow-scan prologue: <=1 cold uint4 per thread, block-reduced,
// one atomicMax per block. Rows >=0, <2^31 => signed word-max exact for both
// index dtypes (int64 high words zero; int32 words all values).
// ---------------------------------------------------------------------------
__global__ __launch_bounds__(512, 2)
void gemm_main_kernel(const float* __restrict__ Zu,
                      const float* __restrict__ Zr,
                      const float* __restrict__ W1,
                      const float* __restrict__ b1,
                      const void* __restrict__ eidx,
                      int E, int gr, int Mu, int Mr)
{
    extern __shared__ __align__(16) char sm[];
    __shared__ int s_wmax[16];

    const int is64 = detect_is64_block((const unsigned long long*)eidx);
    if (blockIdx.x == 0 && threadIdx.x == 0) g_is64 = is64;

    // --- maxrow prologue ---
    {
        const size_t nwords = (size_t)E * (is64 ? 2 : 1);
        const int n4 = (int)(nwords >> 2);
        const uint4* p4 = (const uint4*)eidx;
        const int chunk = (n4 + gridDim.x - 1) / gridDim.x;
        const int beg = blockIdx.x * chunk;
        const int end = min(beg + chunk, n4);
        int m = 0;
        for (int i = beg + threadIdx.x; i < end; i += 512) {
            uint4 a = p4[i];
            m = max(m, max(max((int)a.x, (int)a.y), max((int)a.z, (int)a.w)));
        }
        if (blockIdx.x == 0) {       // scalar word tail
            const int* pw = (const int*)eidx;
            for (int w = (n4 << 2) + threadIdx.x; w < (int)nwords; w += 512)
                m = max(m, pw[w]);
        }
        #pragma unroll
        for (int off = 16; off; off >>= 1)
            m = max(m, __shfl_xor_sync(0xffffffffu, m, off));
        if ((threadIdx.x & 31) == 0) s_wmax[threadIdx.x >> 5] = m;
        __syncthreads();
        if (threadIdx.x < 16) {
            int v = s_wmax[threadIdx.x];
            #pragma unroll
            for (int off = 8; off; off >>= 1)
                v = max(v, __shfl_xor_sync(0xFFFFu, v, off));
            if (threadIdx.x == 0) atomicMax(&g_maxrow, v);
        }
        __syncthreads();
    }

    // --- GEMM tile (single call site to keep register budget) ---
    const bool isU = (blockIdx.x >= (unsigned)gr);
    const int  blk = isU ? (blockIdx.x - gr) : blockIdx.x;
    gemm_tile(isU ? Zu : Zr,
              isU ? W1 : W1 + HDIM * HDIM,
              isU ? b1 : nullptr,
              isU ? g_U : g_R,
              blk * 128,
              isU ? Mu : Mr,
              sm);
}

// ---------------------------------------------------------------------------
// Kernel B: U tiles [K, gu), gated on g_maxrow (normally all skip).
// ---------------------------------------------------------------------------
__global__ __launch_bounds__(512, 2)
void gemm_u_rest_kernel(const float* __restrict__ Zu,
                        const float* __restrict__ W1,
                        const float* __restrict__ b1,
                        int K, int Mu)
{
    extern __shared__ __align__(16) char sm[];
    const int row0 = (K + blockIdx.x) * 128;
    if (row0 > g_maxrow) return;
    gemm_tile(Zu, W1, b1, g_U, row0, Mu, sm);
}

// ---------------------------------------------------------------------------
// Phase 2: four edges per warp (8 lanes each); lane l8 loads chunks l8 and
// l8+8 so each 8-lane LDG.128 group covers one full 128B line.
// ---------------------------------------------------------------------------
__device__ __forceinline__ float dot8h(uint4 u, uint4 r, float4 w0, float4 w1) {
    const __half2 z2 = __float2half2_rn(0.f);
    __half2 a0 = __hmax2(__hadd2(*(__half2*)&u.x, *(__half2*)&r.x), z2);
    __half2 a1 = __hmax2(__hadd2(*(__half2*)&u.y, *(__half2*)&r.y), z2);
    __half2 a2 = __hmax2(__hadd2(*(__half2*)&u.z, *(__half2*)&r.z), z2);
    __half2 a3 = __hmax2(__hadd2(*(__half2*)&u.w, *(__half2*)&r.w), z2);
    float2 f0 = __half22float2(a0);
    float2 f1 = __half22float2(a1);
    float2 f2 = __half22float2(a2);
    float2 f3 = __half22float2(a3);
    float s;
    s  = f0.x * w0.x;
    s  = fmaf(f0.y, w0.y, s);
    s  = fmaf(f1.x, w0.z, s);
    s  = fmaf(f1.y, w0.w, s);
    s  = fmaf(f2.x, w1.x, s);
    s  = fmaf(f2.y, w1.y, s);
    s  = fmaf(f3.x, w1.z, s);
    s  = fmaf(f3.y, w1.w, s);
    return s;
}

__global__ __launch_bounds__(256)
void edge_kernel(const void* __restrict__ eidx,
                 const float* __restrict__ W2,
                 const float* __restrict__ b2,
                 float* __restrict__ out,
                 int E)
{
    __shared__ float w2s[HDIM];
    const int tid = threadIdx.x;
    if (tid < HDIM) w2s[tid] = W2[tid];
    __syncthreads();

    const int warp = (blockIdx.x * 256 + tid) >> 5;
    const int lane = tid & 31;
    const int sub  = lane >> 3;
    const int l8   = lane & 7;
    const int e    = warp * 4 + sub;
    if (e >= E) return;

    int row, col;
    if (g_is64) {
        const long long* p = (const long long*)eidx;
        row = (int)p[e];
        col = (int)p[(size_t)E + e];
    } else {
        const int* p = (const int*)eidx;
        row = p[e];
        col = p[(size_t)E + e];
    }

    const uint4* Up = (const uint4*)&g_U[(size_t)row * HDIM];
    const uint4* Rp = (const uint4*)&g_R[(size_t)col * HDIM];
    const uint4 ua = Up[l8],  ub = Up[l8 + 8];
    const uint4 ra = Rp[l8],  rb = Rp[l8 + 8];

    const float4* w4 = (const float4*)w2s;
    const float4 w0 = w4[2 * l8],      w1 = w4[2 * l8 + 1];
    const float4 w2 = w4[16 + 2 * l8], w3 = w4[16 + 2 * l8 + 1];

    float s = dot8h(ua, ra, w0, w1) + dot8h(ub, rb, w2, w3);

    const unsigned mask = 0xFFu << (sub * 8);
    #pragma unroll
    for (int off = 4; off; off >>= 1)
        s += __shfl_xor_sync(mask, s, off);

    if (l8 == 0) out[e] = s + __ldg(b2);
}

// ---------------------------------------------------------------------------
extern "C" void kernel_launch(void* const* d_in, const int* in_sizes, int n_in,
                              void* d_out, int out_size)
{
    const float* z_user   = (const float*)d_in[0];
    const float* z_recipe = (const float*)d_in[1];
    const void*  eidx     = d_in[2];
    const float* W1       = (const float*)d_in[3];
    const float* b1       = (const float*)d_in[4];
    const float* W2       = (const float*)d_in[5];
    const float* b2       = (const float*)d_in[6];
    float* out = (float*)d_out;

    const int Mu = in_sizes[0] / HDIM;
    const int Mr = in_sizes[1] / HDIM;
    const int E  = in_sizes[2] / 2;

    const int SMEM = 2 * TILEB;
    cudaFuncSetAttribute(gemm_main_kernel,
                         cudaFuncAttributeMaxDynamicSharedMemorySize, SMEM);
    cudaFuncSetAttribute(gemm_u_rest_kernel,
                         cudaFuncAttributeMaxDynamicSharedMemorySize, SMEM);

    const int gu = (Mu + 127) / 128;
    const int gr = (Mr + 127) / 128;
    const int K  = (gu < gr) ? gu : gr;     // unconditional U tiles

    gemm_main_kernel<<<gr + K, 512, SMEM>>>(z_user, z_recipe, W1, b1,
                                            eidx, E, gr, Mu, Mr);
    if (gu > K)
        gemm_u_rest_kernel<<<gu - K, 512, SMEM>>>(z_user, W1, b1, K, Mu);
    edge_kernel<<<(E + 31) / 32, 256>>>(eidx, W2, b2, out, E);
}